// round 1
// baseline (speedup 1.0000x reference)
#include <cuda_runtime.h>
#include <cstdint>

// Problem constants (fixed by setup_inputs)
#define BATCH 8
#define H 1024
#define W 1024
#define HW (H*W)
#define TH 512
#define TW 512
#define NCELL (TH*TW)          // 262144 = 2^18
#define COORDS_ELEMS (BATCH*NCELL*4*2)   // 16777216
#define WEIGHTS_ELEMS (BATCH*NCELL*4)    // 8388608
#define DENS_ELEMS (BATCH*HW)            // 8388608

// Scratch (static device globals — allocation-free per harness rules)
__device__ float g_gray[BATCH*HW];
__device__ float g_contrast[BATCH*HW];
__device__ unsigned g_mn[BATCH];
__device__ unsigned g_mx[BATCH];

// ---------------------------------------------------------------------------
// JAX threefry2x32, key = jax.random.key(42) -> (0, 42)
// ks2 = 0 ^ 42 ^ 0x1BD11BDA = 0x1BD11BF0
// ---------------------------------------------------------------------------
__device__ __forceinline__ unsigned rotl32(unsigned x, int r) {
    return __funnelshift_l(x, x, r);
}

__device__ __forceinline__ void threefry2x32(unsigned x0, unsigned x1,
                                             unsigned& o0, unsigned& o1) {
    const unsigned ks0 = 0u, ks1 = 42u, ks2 = 0x1BD11BF0u;
    x0 += ks0; x1 += ks1;
#define TFR(r) { x0 += x1; x1 = rotl32(x1, r); x1 ^= x0; }
    TFR(13) TFR(15) TFR(26) TFR(6)
    x0 += ks1; x1 += ks2 + 1u;
    TFR(17) TFR(29) TFR(16) TFR(24)
    x0 += ks2; x1 += ks0 + 2u;
    TFR(13) TFR(15) TFR(26) TFR(6)
    x0 += ks0; x1 += ks1 + 3u;
    TFR(17) TFR(29) TFR(16) TFR(24)
    x0 += ks1; x1 += ks2 + 4u;
    TFR(13) TFR(15) TFR(26) TFR(6)
    x0 += ks2; x1 += ks0 + 5u;
#undef TFR
    o0 = x0; o1 = x1;
}

// partitionable threefry random bits (bit_width=32): counter = flat index,
// hi32 = 0, lo32 = i, bits = out0 ^ out1
__device__ __forceinline__ float tf_uniform(unsigned flat_idx) {
    unsigned o0, o1;
    threefry2x32(0u, flat_idx, o0, o1);
    unsigned bits = o0 ^ o1;
    return __uint_as_float((bits >> 9) | 0x3f800000u) - 1.0f;
}

// ---------------------------------------------------------------------------
// Kernel 0: reset per-batch min/max (floats are >0 so uint ordering works)
// ---------------------------------------------------------------------------
__global__ void k_init() {
    int i = threadIdx.x;
    if (i < BATCH) { g_mn[i] = 0x7F800000u; g_mx[i] = 0u; }
}

// ---------------------------------------------------------------------------
// Kernel 1: gray = 0.299 R + 0.587 G + 0.114 B
// ---------------------------------------------------------------------------
__global__ void k_gray(const float* __restrict__ img) {
    int i = blockIdx.x * blockDim.x + threadIdx.x;
    if (i >= BATCH*HW) return;
    int b = i >> 20;
    int p = i & (HW - 1);
    const float* base = img + (size_t)b * 3 * HW + p;
    float r  = __ldg(base);
    float g  = __ldg(base + HW);
    float bl = __ldg(base + 2 * HW);
    g_gray[i] = r * 0.299f + g * 0.587f + bl * 0.114f;
}

// ---------------------------------------------------------------------------
// Kernel 2: contrast = 0.5*sobel + 0.3*|lapl| + 0.2*gradm, plus per-batch
// min/max reduction (block reduce + one atomic pair per block).
// Convs are zero-padded (lax.conv), grad uses edge-clamped central diff.
// ---------------------------------------------------------------------------
__device__ __forceinline__ float gpix(const float* g, int y, int x) {
    return ((unsigned)y < H && (unsigned)x < W) ? g[y * W + x] : 0.0f;
}

__global__ void k_contrast() {
    int i = blockIdx.x * blockDim.x + threadIdx.x;
    int b = i >> 20;
    int p = i & (HW - 1);
    int y = p >> 10;
    int x = p & (W - 1);
    const float* g = g_gray + b * HW;

    float a00 = gpix(g, y-1, x-1), a01 = gpix(g, y-1, x), a02 = gpix(g, y-1, x+1);
    float a10 = gpix(g, y,   x-1), a11 = g[p],            a12 = gpix(g, y,   x+1);
    float a20 = gpix(g, y+1, x-1), a21 = gpix(g, y+1, x), a22 = gpix(g, y+1, x+1);

    float gx = (a02 - a00) + 2.0f * (a12 - a10) + (a22 - a20);
    float gy = (a20 - a00) + 2.0f * (a21 - a01) + (a22 - a02);
    float sobel = sqrtf(gx * gx + gy * gy + 1e-8f);
    float lapl  = fabsf(4.0f * a11 - a01 - a10 - a12 - a21);

    // edge-padded central differences
    int xl = (x == 0) ? 0 : ((x == W-1) ? W-3 : x-1);
    int xr = (x == 0) ? 2 : ((x == W-1) ? W-1 : x+1);
    int yl = (y == 0) ? 0 : ((y == H-1) ? H-3 : y-1);
    int yr = (y == 0) ? 2 : ((y == H-1) ? H-1 : y+1);
    float dx = g[y * W + xr] - g[y * W + xl];
    float dy = g[yr * W + x] - g[yl * W + x];
    float gradm = sqrtf(dx * dx + dy * dy + 1e-8f);

    float c = 0.5f * sobel + 0.3f * lapl + 0.2f * gradm;
    g_contrast[i] = c;

    // block min/max reduce (block fully inside one batch: 1M % 256 == 0)
    __shared__ float smn[256], smx[256];
    int tid = threadIdx.x;
    smn[tid] = c; smx[tid] = c;
    __syncthreads();
    for (int s = 128; s > 0; s >>= 1) {
        if (tid < s) {
            smn[tid] = fminf(smn[tid], smn[tid + s]);
            smx[tid] = fmaxf(smx[tid], smx[tid + s]);
        }
        __syncthreads();
    }
    if (tid == 0) {
        atomicMin(&g_mn[b], __float_as_uint(smn[0]));
        atomicMax(&g_mx[b], __float_as_uint(smx[0]));
    }
}

// ---------------------------------------------------------------------------
// Kernel 3: normalize + 5x5 gaussian (zero-padded) + density remap
// density = 0.1 + 0.9 * sqrt(max(sm, 0))
// ---------------------------------------------------------------------------
__global__ void k_density(float* __restrict__ dens_out) {
    int i = blockIdx.x * blockDim.x + threadIdx.x;
    if (i >= BATCH*HW) return;
    int b = i >> 20;
    int p = i & (HW - 1);
    int y = p >> 10;
    int x = p & (W - 1);

    float mn = __uint_as_float(g_mn[b]);
    float mx = __uint_as_float(g_mx[b]);
    bool ok = mx > mn;
    float inv = ok ? 1.0f / (mx - mn) : 0.0f;

    // gaussian kernel, sigma = 5/6, normalized (matches jnp float32 path
    // to within ulps)
    float sg = 5.0f / 6.0f;
    float s2 = sg * sg;
    float e1 = expf(-0.5f / s2);
    float e2 = expf(-2.0f / s2);
    float ksum = 1.0f + 2.0f * e1 + 2.0f * e2;
    float w[5];
    w[0] = e2 / ksum; w[1] = e1 / ksum; w[2] = 1.0f / ksum; w[3] = w[1]; w[4] = w[0];

    const float* cb = g_contrast + b * HW;
    float acc = 0.0f;
#pragma unroll
    for (int dy = -2; dy <= 2; ++dy) {
#pragma unroll
        for (int dx = -2; dx <= 2; ++dx) {
            int yy = y + dy, xx = x + dx;
            if ((unsigned)yy < H && (unsigned)xx < W) {
                float nv = ok ? (cb[yy * W + xx] - mn) * inv : 0.0f;
                acc += w[dy + 2] * w[dx + 2] * nv;
            }
        }
    }
    dens_out[i] = 0.1f + 0.9f * sqrtf(fmaxf(acc, 0.0f));
}

// ---------------------------------------------------------------------------
// Kernel 4: adaptive coords + weights. One thread per (b, i, j) cell.
// Flat uniform index for (b,i,j,s,c) = (((b*512+i)*512+j)*4+s)*2+c = t*8 + k
// ---------------------------------------------------------------------------
__global__ void k_coords(const float* __restrict__ dens,
                         float* __restrict__ coords,
                         float* __restrict__ weights) {
    int t = blockIdx.x * blockDim.x + threadIdx.x;
    if (t >= BATCH * NCELL) return;
    int b = t >> 18;
    int cell = t & (NCELL - 1);
    int i = cell >> 9;
    int j = cell & (TW - 1);

    unsigned ctr = (unsigned)t * 8u;
    float u[8];
#pragma unroll
    for (int s = 0; s < 8; ++s) u[s] = tf_uniform(ctr + s);

    float d = dens[b * HW + (i << 1) * W + (j << 1)];
    int ns = (d > 0.7f) ? 4 : ((d > 0.4f) ? 2 : 1);
    float useoff = (ns > 1) ? 1.0f : 0.0f;
    float wv = d / (float)ns;

    float by = -1.0f + (float)i * (2.0f / 511.0f);
    float bx = -1.0f + (float)j * (2.0f / 511.0f);
    // off = ((u - 0.5) * 0.8) * cell,  cell = 2/512 = 2^-8 (exact)
    const float CELLSZ = 0.00390625f;

    float4 c0, c1;
    c0.x = by + useoff * (((u[0] - 0.5f) * 0.8f) * CELLSZ);
    c0.y = bx + useoff * (((u[1] - 0.5f) * 0.8f) * CELLSZ);
    c0.z = by + useoff * (((u[2] - 0.5f) * 0.8f) * CELLSZ);
    c0.w = bx + useoff * (((u[3] - 0.5f) * 0.8f) * CELLSZ);
    c1.x = by + useoff * (((u[4] - 0.5f) * 0.8f) * CELLSZ);
    c1.y = bx + useoff * (((u[5] - 0.5f) * 0.8f) * CELLSZ);
    c1.z = by + useoff * (((u[6] - 0.5f) * 0.8f) * CELLSZ);
    c1.w = bx + useoff * (((u[7] - 0.5f) * 0.8f) * CELLSZ);

    float4* cp = (float4*)coords;
    cp[(size_t)t * 2]     = c0;
    cp[(size_t)t * 2 + 1] = c1;

    float4 w4;
    w4.x = wv;                          // sample 0 always valid
    w4.y = (ns > 1) ? wv : 0.0f;
    w4.z = (ns > 3) ? wv : 0.0f;
    w4.w = (ns > 3) ? wv : 0.0f;
    ((float4*)weights)[t] = w4;
}

// ---------------------------------------------------------------------------
extern "C" void kernel_launch(void* const* d_in, const int* in_sizes, int n_in,
                              void* d_out, int out_size) {
    const float* img = (const float*)d_in[0];
    float* out = (float*)d_out;
    float* coords  = out;
    float* weights = out + COORDS_ELEMS;
    float* dens    = out + COORDS_ELEMS + WEIGHTS_ELEMS;

    k_init<<<1, 32>>>();
    k_gray<<<(BATCH*HW)/256, 256>>>(img);
    k_contrast<<<(BATCH*HW)/256, 256>>>();
    k_density<<<(BATCH*HW)/256, 256>>>(dens);
    k_coords<<<(BATCH*NCELL)/256, 256>>>(dens, coords, weights);
}

// round 2
// speedup vs baseline: 1.5599x; 1.5599x over previous
#include <cuda_runtime.h>
#include <cstdint>

// Problem constants (fixed by setup_inputs)
#define BATCH 8
#define H 1024
#define W 1024
#define HW (H*W)
#define TH 512
#define TW 512
#define NCELL (TH*TW)                    // 262144 = 2^18
#define COORDS_ELEMS (BATCH*NCELL*4*2)   // 16777216
#define WEIGHTS_ELEMS (BATCH*NCELL*4)    // 8388608

// Scratch (static device globals — allocation-free per harness rules)
__device__ float g_contrast[BATCH*HW];
__device__ unsigned g_mn[BATCH];
__device__ unsigned g_mx[BATCH];

// ---------------------------------------------------------------------------
// JAX threefry2x32, key = jax.random.key(42) -> (0, 42)
// ---------------------------------------------------------------------------
__device__ __forceinline__ unsigned rotl32(unsigned x, int r) {
    return __funnelshift_l(x, x, r);
}

__device__ __forceinline__ void threefry2x32(unsigned x0, unsigned x1,
                                             unsigned& o0, unsigned& o1) {
    const unsigned ks0 = 0u, ks1 = 42u, ks2 = 0x1BD11BF0u;
    x0 += ks0; x1 += ks1;
#define TFR(r) { x0 += x1; x1 = rotl32(x1, r); x1 ^= x0; }
    TFR(13) TFR(15) TFR(26) TFR(6)
    x0 += ks1; x1 += ks2 + 1u;
    TFR(17) TFR(29) TFR(16) TFR(24)
    x0 += ks2; x1 += ks0 + 2u;
    TFR(13) TFR(15) TFR(26) TFR(6)
    x0 += ks0; x1 += ks1 + 3u;
    TFR(17) TFR(29) TFR(16) TFR(24)
    x0 += ks1; x1 += ks2 + 4u;
    TFR(13) TFR(15) TFR(26) TFR(6)
    x0 += ks2; x1 += ks0 + 5u;
#undef TFR
    o0 = x0; o1 = x1;
}

__device__ __forceinline__ float tf_uniform(unsigned flat_idx) {
    unsigned o0, o1;
    threefry2x32(0u, flat_idx, o0, o1);
    unsigned bits = o0 ^ o1;
    return __uint_as_float((bits >> 9) | 0x3f800000u) - 1.0f;
}

// ---------------------------------------------------------------------------
// Kernel 0: reset per-batch min/max (must run every call: graph replays)
// ---------------------------------------------------------------------------
__global__ void k_init() {
    int i = threadIdx.x;
    if (i < BATCH) { g_mn[i] = 0x7F800000u; g_mx[i] = 0u; }
}

// ---------------------------------------------------------------------------
// Kernel 1 (fused gray + contrast + per-batch min/max reduction)
// Tile: 32x8 outputs, gray halo of 2 -> smem 36x12, gray computed from img.
// Out-of-image gray = 0 (matches zero-padded conv); edge-diff indices are
// always in-image and within the halo.
// ---------------------------------------------------------------------------
__global__ void k_contrast(const float* __restrict__ img) {
    __shared__ float sg[12][36];
    const int b   = blockIdx.z;
    const int bx0 = blockIdx.x * 32;
    const int by0 = blockIdx.y * 8;
    const int tx = threadIdx.x, ty = threadIdx.y;
    const int lin = ty * 32 + tx;

    const float* ib = img + (size_t)b * 3 * HW;

    // load 36x12 gray tile (432 entries, 256 threads)
    for (int e = lin; e < 12 * 36; e += 256) {
        int r = e / 36, c = e % 36;
        int gy = by0 + r - 2, gx = bx0 + c - 2;
        float v = 0.0f;
        if ((unsigned)gy < H && (unsigned)gx < W) {
            int p = gy * W + gx;
            v = __ldg(ib + p) * 0.299f + __ldg(ib + HW + p) * 0.587f
              + __ldg(ib + 2 * HW + p) * 0.114f;
        }
        sg[r][c] = v;
    }
    __syncthreads();

    const int x = bx0 + tx, y = by0 + ty;
    const int lx = tx + 2, ly = ty + 2;

    float a00 = sg[ly-1][lx-1], a01 = sg[ly-1][lx], a02 = sg[ly-1][lx+1];
    float a10 = sg[ly  ][lx-1], a11 = sg[ly  ][lx], a12 = sg[ly  ][lx+1];
    float a20 = sg[ly+1][lx-1], a21 = sg[ly+1][lx], a22 = sg[ly+1][lx+1];

    float gx2 = (a02 - a00) + 2.0f * (a12 - a10) + (a22 - a20);
    float gy2 = (a20 - a00) + 2.0f * (a21 - a01) + (a22 - a02);
    float sobel = sqrtf(gx2 * gx2 + gy2 * gy2 + 1e-8f);
    float lapl  = fabsf(4.0f * a11 - a01 - a10 - a12 - a21);

    // edge-padded central differences (clamped indices, always within halo)
    int xl = (x == 0) ? 0 : ((x == W-1) ? W-3 : x-1);
    int xr = (x == 0) ? 2 : ((x == W-1) ? W-1 : x+1);
    int yl = (y == 0) ? 0 : ((y == H-1) ? H-3 : y-1);
    int yr = (y == 0) ? 2 : ((y == H-1) ? H-1 : y+1);
    float dx = sg[ly][xr - bx0 + 2] - sg[ly][xl - bx0 + 2];
    float dy = sg[yr - by0 + 2][lx] - sg[yl - by0 + 2][lx];
    float gradm = sqrtf(dx * dx + dy * dy + 1e-8f);

    float c = 0.5f * sobel + 0.3f * lapl + 0.2f * gradm;
    g_contrast[b * HW + y * W + x] = c;

    // block min/max reduce + one atomic pair (block within one batch)
    __shared__ float smn[256], smx[256];
    smn[lin] = c; smx[lin] = c;
    __syncthreads();
    for (int s = 128; s > 0; s >>= 1) {
        if (lin < s) {
            smn[lin] = fminf(smn[lin], smn[lin + s]);
            smx[lin] = fmaxf(smx[lin], smx[lin + s]);
        }
        __syncthreads();
    }
    if (lin == 0) {
        atomicMin(&g_mn[b], __float_as_uint(smn[0]));
        atomicMax(&g_mx[b], __float_as_uint(smx[0]));
    }
}

// ---------------------------------------------------------------------------
// Kernel 2: separable 5x5 gaussian with normalization folded out.
//   sm = inv * ( conv2(w, c) - mn * wyv(y)*wxv(x) )
//   density = 0.1 + 0.9*sqrt(max(sm,0))
// Tile 32x32 outputs, block 32x8 (each thread 4 rows), halo 2.
// ---------------------------------------------------------------------------
__global__ void k_density(float* __restrict__ dens_out) {
    __shared__ float raw[36][36];
    __shared__ float hac[36][32];

    const int b   = blockIdx.z;
    const int bx0 = blockIdx.x * 32;
    const int by0 = blockIdx.y * 32;
    const int tx = threadIdx.x, ty = threadIdx.y;
    const int lin = ty * 32 + tx;

    // gaussian weights (same fp path as reference, ~ulp identical)
    const float sg2 = (5.0f / 6.0f) * (5.0f / 6.0f);
    const float e1 = expf(-0.5f / sg2);
    const float e2 = expf(-2.0f / sg2);
    const float ksum = 1.0f + 2.0f * e1 + 2.0f * e2;
    float w[5];
    w[0] = e2 / ksum; w[1] = e1 / ksum; w[2] = 1.0f / ksum; w[3] = w[1]; w[4] = w[0];

    const float* cb = g_contrast + b * HW;

    // load 36x36 contrast tile (zero outside image)
    for (int e = lin; e < 36 * 36; e += 256) {
        int r = e / 36, c = e % 36;
        int gy = by0 + r - 2, gx = bx0 + c - 2;
        raw[r][c] = ((unsigned)gy < H && (unsigned)gx < W) ? cb[gy * W + gx] : 0.0f;
    }
    __syncthreads();

    // horizontal pass: 36 rows x 32 cols
    for (int e = lin; e < 36 * 32; e += 256) {
        int r = e >> 5, c = e & 31;
        float a = w[0] * raw[r][c]     + w[1] * raw[r][c + 1]
                + w[2] * raw[r][c + 2] + w[3] * raw[r][c + 3]
                + w[4] * raw[r][c + 4];
        hac[r][c] = a;
    }
    __syncthreads();

    const float mn = __uint_as_float(g_mn[b]);
    const float mx = __uint_as_float(g_mx[b]);
    const bool ok = mx > mn;
    const float inv = ok ? 1.0f / (mx - mn) : 0.0f;

    const int x = bx0 + tx;
    // valid-weight sum along x (border-only deviation from 1)
    float wxv = 0.0f;
#pragma unroll
    for (int d = 0; d < 5; ++d)
        if ((unsigned)(x + d - 2) < W) wxv += w[d];

#pragma unroll
    for (int k = 0; k < 4; ++k) {
        int ry = ty + 8 * k;
        int y = by0 + ry;
        float acc = w[0] * hac[ry][tx]     + w[1] * hac[ry + 1][tx]
                  + w[2] * hac[ry + 2][tx] + w[3] * hac[ry + 3][tx]
                  + w[4] * hac[ry + 4][tx];
        float wyv = 0.0f;
#pragma unroll
        for (int d = 0; d < 5; ++d)
            if ((unsigned)(y + d - 2) < H) wyv += w[d];
        float sm = inv * (acc - mn * (wyv * wxv));
        dens_out[b * HW + y * W + x] = 0.1f + 0.9f * sqrtf(fmaxf(sm, 0.0f));
    }
}

// ---------------------------------------------------------------------------
// Kernel 3: adaptive coords + weights. One thread per (b, i, j) cell.
// When ns==1 the random offsets are multiplied by 0 -> skip all 8 threefrys.
// ---------------------------------------------------------------------------
__global__ void k_coords(const float* __restrict__ dens,
                         float* __restrict__ coords,
                         float* __restrict__ weights) {
    int t = blockIdx.x * blockDim.x + threadIdx.x;
    if (t >= BATCH * NCELL) return;
    int b = t >> 18;
    int cell = t & (NCELL - 1);
    int i = cell >> 9;
    int j = cell & (TW - 1);

    float d = dens[b * HW + (i << 1) * W + (j << 1)];
    int ns = (d > 0.7f) ? 4 : ((d > 0.4f) ? 2 : 1);
    float wv = d / (float)ns;

    float by = -1.0f + (float)i * (2.0f / 511.0f);
    float bx = -1.0f + (float)j * (2.0f / 511.0f);
    const float CELLSZ = 0.00390625f;   // 2/512 exact

    float4 c0, c1;
    if (ns > 1) {
        unsigned ctr = (unsigned)t * 8u;
        float u[8];
#pragma unroll
        for (int s = 0; s < 8; ++s) u[s] = tf_uniform(ctr + s);
        c0.x = by + ((u[0] - 0.5f) * 0.8f) * CELLSZ;
        c0.y = bx + ((u[1] - 0.5f) * 0.8f) * CELLSZ;
        c0.z = by + ((u[2] - 0.5f) * 0.8f) * CELLSZ;
        c0.w = bx + ((u[3] - 0.5f) * 0.8f) * CELLSZ;
        c1.x = by + ((u[4] - 0.5f) * 0.8f) * CELLSZ;
        c1.y = bx + ((u[5] - 0.5f) * 0.8f) * CELLSZ;
        c1.z = by + ((u[6] - 0.5f) * 0.8f) * CELLSZ;
        c1.w = bx + ((u[7] - 0.5f) * 0.8f) * CELLSZ;
    } else {
        c0.x = by; c0.y = bx; c0.z = by; c0.w = bx;
        c1.x = by; c1.y = bx; c1.z = by; c1.w = bx;
    }

    float4* cp = (float4*)coords;
    cp[(size_t)t * 2]     = c0;
    cp[(size_t)t * 2 + 1] = c1;

    float4 w4;
    w4.x = wv;
    w4.y = (ns > 1) ? wv : 0.0f;
    w4.z = (ns > 3) ? wv : 0.0f;
    w4.w = (ns > 3) ? wv : 0.0f;
    ((float4*)weights)[t] = w4;
}

// ---------------------------------------------------------------------------
extern "C" void kernel_launch(void* const* d_in, const int* in_sizes, int n_in,
                              void* d_out, int out_size) {
    const float* img = (const float*)d_in[0];
    float* out = (float*)d_out;
    float* coords  = out;
    float* weights = out + COORDS_ELEMS;
    float* dens    = out + COORDS_ELEMS + WEIGHTS_ELEMS;

    k_init<<<1, 32>>>();
    {
        dim3 grid(W / 32, H / 8, BATCH), block(32, 8);
        k_contrast<<<grid, block>>>(img);
    }
    {
        dim3 grid(W / 32, H / 32, BATCH), block(32, 8);
        k_density<<<grid, block>>>(dens);
    }
    k_coords<<<(BATCH*NCELL)/256, 256>>>(dens, coords, weights);
}

// round 3
// speedup vs baseline: 1.9767x; 1.2672x over previous
#include <cuda_runtime.h>
#include <cstdint>

// Problem constants (fixed by setup_inputs)
#define BATCH 8
#define H 1024
#define W 1024
#define HW (H*W)
#define TH 512
#define TW 512
#define NCELL (TH*TW)                    // 262144 = 2^18
#define COORDS_ELEMS (BATCH*NCELL*4*2)   // 16777216
#define WEIGHTS_ELEMS (BATCH*NCELL*4)    // 8388608

// Scratch (static device globals — allocation-free per harness rules)
__device__ float g_contrast[BATCH*HW];
__device__ unsigned g_mn[BATCH];
__device__ unsigned g_mx[BATCH];

// ---------------------------------------------------------------------------
// JAX threefry2x32, key = jax.random.key(42) -> (0, 42)
// ---------------------------------------------------------------------------
__device__ __forceinline__ unsigned rotl32(unsigned x, int r) {
    return __funnelshift_l(x, x, r);
}

__device__ __forceinline__ void threefry2x32(unsigned x0, unsigned x1,
                                             unsigned& o0, unsigned& o1) {
    const unsigned ks0 = 0u, ks1 = 42u, ks2 = 0x1BD11BF0u;
    x0 += ks0; x1 += ks1;
#define TFR(r) { x0 += x1; x1 = rotl32(x1, r); x1 ^= x0; }
    TFR(13) TFR(15) TFR(26) TFR(6)
    x0 += ks1; x1 += ks2 + 1u;
    TFR(17) TFR(29) TFR(16) TFR(24)
    x0 += ks2; x1 += ks0 + 2u;
    TFR(13) TFR(15) TFR(26) TFR(6)
    x0 += ks0; x1 += ks1 + 3u;
    TFR(17) TFR(29) TFR(16) TFR(24)
    x0 += ks1; x1 += ks2 + 4u;
    TFR(13) TFR(15) TFR(26) TFR(6)
    x0 += ks2; x1 += ks0 + 5u;
#undef TFR
    o0 = x0; o1 = x1;
}

__device__ __forceinline__ float tf_uniform(unsigned flat_idx) {
    unsigned o0, o1;
    threefry2x32(0u, flat_idx, o0, o1);
    unsigned bits = o0 ^ o1;
    return __uint_as_float((bits >> 9) | 0x3f800000u) - 1.0f;
}

// ---------------------------------------------------------------------------
// Kernel 0: reset per-batch min/max (must run every call: graph replays)
// ---------------------------------------------------------------------------
__global__ void k_init() {
    int i = threadIdx.x;
    if (i < BATCH) { g_mn[i] = 0x7F800000u; g_mx[i] = 0u; }
}

// ---------------------------------------------------------------------------
// Kernel 1: fused gray + contrast + per-batch min/max.
// Tile 32x32 outputs per block (block 32x8, 4 rows/thread), gray halo 2 ->
// smem 36x36 gray computed straight from img. Zero-pad outside image
// (matches lax.conv); central-diff uses edge-clamped indices (within halo).
// Reduction: warp shuffle -> smem 8-entry fold -> 1 atomic pair per block.
// ---------------------------------------------------------------------------
__global__ void k_contrast(const float* __restrict__ img) {
    __shared__ float sg[36][37];
    __shared__ float wmn[8], wmx[8];

    const int b   = blockIdx.z;
    const int bx0 = blockIdx.x * 32;
    const int by0 = blockIdx.y * 32;
    const int tx = threadIdx.x, ty = threadIdx.y;
    const int lin = ty * 32 + tx;

    const float* ib = img + (size_t)b * 3 * HW;

    // load 36x36 gray tile (1296 entries, 256 threads)
    for (int e = lin; e < 36 * 36; e += 256) {
        int r = e / 36, c = e - r * 36;
        int gy = by0 + r - 2, gx = bx0 + c - 2;
        float v = 0.0f;
        if ((unsigned)gy < H && (unsigned)gx < W) {
            int p = gy * W + gx;
            v = __ldg(ib + p) * 0.299f + __ldg(ib + HW + p) * 0.587f
              + __ldg(ib + 2 * HW + p) * 0.114f;
        }
        sg[r][c] = v;
    }
    __syncthreads();

    const int x = bx0 + tx;
    const int lx = tx + 2;
    // x-direction clamped diff indices (shared across the 4 rows)
    int xl = (x == 0) ? 0 : ((x == W-1) ? W-3 : x-1);
    int xr = (x == 0) ? 2 : ((x == W-1) ? W-1 : x+1);
    const int lxl = xl - bx0 + 2, lxr = xr - bx0 + 2;

    float cmin = 3.402823466e+38f, cmax = 0.0f;

#pragma unroll
    for (int k = 0; k < 4; ++k) {
        const int ry = ty + 8 * k;
        const int y = by0 + ry;
        const int ly = ry + 2;

        float a00 = sg[ly-1][lx-1], a01 = sg[ly-1][lx], a02 = sg[ly-1][lx+1];
        float a10 = sg[ly  ][lx-1], a11 = sg[ly  ][lx], a12 = sg[ly  ][lx+1];
        float a20 = sg[ly+1][lx-1], a21 = sg[ly+1][lx], a22 = sg[ly+1][lx+1];

        float gx2 = (a02 - a00) + 2.0f * (a12 - a10) + (a22 - a20);
        float gy2 = (a20 - a00) + 2.0f * (a21 - a01) + (a22 - a02);
        float sobel = sqrtf(gx2 * gx2 + gy2 * gy2 + 1e-8f);
        float lapl  = fabsf(4.0f * a11 - a01 - a10 - a12 - a21);

        int yl = (y == 0) ? 0 : ((y == H-1) ? H-3 : y-1);
        int yr = (y == 0) ? 2 : ((y == H-1) ? H-1 : y+1);
        float dx = sg[ly][lxr] - sg[ly][lxl];
        float dy = sg[yl - by0 + 2][lx];
        dy = sg[yr - by0 + 2][lx] - dy;
        float gradm = sqrtf(dx * dx + dy * dy + 1e-8f);

        float c = 0.5f * sobel + 0.3f * lapl + 0.2f * gradm;
        g_contrast[b * HW + y * W + x] = c;
        cmin = fminf(cmin, c);
        cmax = fmaxf(cmax, c);
    }

    // warp shuffle reduce
#pragma unroll
    for (int s = 16; s > 0; s >>= 1) {
        cmin = fminf(cmin, __shfl_xor_sync(0xFFFFFFFFu, cmin, s));
        cmax = fmaxf(cmax, __shfl_xor_sync(0xFFFFFFFFu, cmax, s));
    }
    if (tx == 0) { wmn[ty] = cmin; wmx[ty] = cmax; }
    __syncthreads();
    if (lin == 0) {
        float mn = wmn[0], mx = wmx[0];
#pragma unroll
        for (int s = 1; s < 8; ++s) {
            mn = fminf(mn, wmn[s]);
            mx = fmaxf(mx, wmx[s]);
        }
        atomicMin(&g_mn[b], __float_as_uint(mn));
        atomicMax(&g_mx[b], __float_as_uint(mx));
    }
}

// ---------------------------------------------------------------------------
// Kernel 2: separable 5x5 gaussian with normalization folded out.
//   sm = inv * ( conv2(w, c) - mn * wyv(y)*wxv(x) )
//   density = 0.1 + 0.9*sqrt(max(sm,0))
// Tile 32x32 outputs, block 32x8 (each thread 4 rows), halo 2.
// ---------------------------------------------------------------------------
__global__ void k_density(float* __restrict__ dens_out) {
    __shared__ float raw[36][36];
    __shared__ float hac[36][32];

    const int b   = blockIdx.z;
    const int bx0 = blockIdx.x * 32;
    const int by0 = blockIdx.y * 32;
    const int tx = threadIdx.x, ty = threadIdx.y;
    const int lin = ty * 32 + tx;

    // gaussian weights (same fp path as reference, ~ulp identical)
    const float sg2 = (5.0f / 6.0f) * (5.0f / 6.0f);
    const float e1 = expf(-0.5f / sg2);
    const float e2 = expf(-2.0f / sg2);
    const float ksum = 1.0f + 2.0f * e1 + 2.0f * e2;
    float w[5];
    w[0] = e2 / ksum; w[1] = e1 / ksum; w[2] = 1.0f / ksum; w[3] = w[1]; w[4] = w[0];

    const float* cb = g_contrast + b * HW;

    // load 36x36 contrast tile (zero outside image)
    for (int e = lin; e < 36 * 36; e += 256) {
        int r = e / 36, c = e - r * 36;
        int gy = by0 + r - 2, gx = bx0 + c - 2;
        raw[r][c] = ((unsigned)gy < H && (unsigned)gx < W) ? cb[gy * W + gx] : 0.0f;
    }
    __syncthreads();

    // horizontal pass: 36 rows x 32 cols
    for (int e = lin; e < 36 * 32; e += 256) {
        int r = e >> 5, c = e & 31;
        float a = w[0] * raw[r][c]     + w[1] * raw[r][c + 1]
                + w[2] * raw[r][c + 2] + w[3] * raw[r][c + 3]
                + w[4] * raw[r][c + 4];
        hac[r][c] = a;
    }
    __syncthreads();

    const float mn = __uint_as_float(g_mn[b]);
    const float mx = __uint_as_float(g_mx[b]);
    const bool ok = mx > mn;
    const float inv = ok ? 1.0f / (mx - mn) : 0.0f;

    const int x = bx0 + tx;
    float wxv = 0.0f;
#pragma unroll
    for (int d = 0; d < 5; ++d)
        if ((unsigned)(x + d - 2) < W) wxv += w[d];

#pragma unroll
    for (int k = 0; k < 4; ++k) {
        int ry = ty + 8 * k;
        int y = by0 + ry;
        float acc = w[0] * hac[ry][tx]     + w[1] * hac[ry + 1][tx]
                  + w[2] * hac[ry + 2][tx] + w[3] * hac[ry + 3][tx]
                  + w[4] * hac[ry + 4][tx];
        float wyv = 0.0f;
#pragma unroll
        for (int d = 0; d < 5; ++d)
            if ((unsigned)(y + d - 2) < H) wyv += w[d];
        float sm = inv * (acc - mn * (wyv * wxv));
        dens_out[b * HW + y * W + x] = 0.1f + 0.9f * sqrtf(fmaxf(sm, 0.0f));
    }
}

// ---------------------------------------------------------------------------
// Kernel 3: adaptive coords + weights. One thread per (b, i, j) cell.
// When ns==1 the random offsets are multiplied by 0 -> skip all 8 threefrys.
// ---------------------------------------------------------------------------
__global__ void k_coords(const float* __restrict__ dens,
                         float* __restrict__ coords,
                         float* __restrict__ weights) {
    int t = blockIdx.x * blockDim.x + threadIdx.x;
    if (t >= BATCH * NCELL) return;
    int b = t >> 18;
    int cell = t & (NCELL - 1);
    int i = cell >> 9;
    int j = cell & (TW - 1);

    float d = __ldg(dens + b * HW + (i << 1) * W + (j << 1));
    int ns = (d > 0.7f) ? 4 : ((d > 0.4f) ? 2 : 1);
    float wv = d / (float)ns;

    float by = -1.0f + (float)i * (2.0f / 511.0f);
    float bx = -1.0f + (float)j * (2.0f / 511.0f);
    const float CELLSZ = 0.00390625f;   // 2/512 exact

    float4 c0, c1;
    if (ns > 1) {
        unsigned ctr = (unsigned)t * 8u;
        float u[8];
#pragma unroll
        for (int s = 0; s < 8; ++s) u[s] = tf_uniform(ctr + s);
        c0.x = by + ((u[0] - 0.5f) * 0.8f) * CELLSZ;
        c0.y = bx + ((u[1] - 0.5f) * 0.8f) * CELLSZ;
        c0.z = by + ((u[2] - 0.5f) * 0.8f) * CELLSZ;
        c0.w = bx + ((u[3] - 0.5f) * 0.8f) * CELLSZ;
        c1.x = by + ((u[4] - 0.5f) * 0.8f) * CELLSZ;
        c1.y = bx + ((u[5] - 0.5f) * 0.8f) * CELLSZ;
        c1.z = by + ((u[6] - 0.5f) * 0.8f) * CELLSZ;
        c1.w = bx + ((u[7] - 0.5f) * 0.8f) * CELLSZ;
    } else {
        c0.x = by; c0.y = bx; c0.z = by; c0.w = bx;
        c1.x = by; c1.y = bx; c1.z = by; c1.w = bx;
    }

    float4* cp = (float4*)coords;
    cp[(size_t)t * 2]     = c0;
    cp[(size_t)t * 2 + 1] = c1;

    float4 w4;
    w4.x = wv;
    w4.y = (ns > 1) ? wv : 0.0f;
    w4.z = (ns > 3) ? wv : 0.0f;
    w4.w = (ns > 3) ? wv : 0.0f;
    ((float4*)weights)[t] = w4;
}

// ---------------------------------------------------------------------------
extern "C" void kernel_launch(void* const* d_in, const int* in_sizes, int n_in,
                              void* d_out, int out_size) {
    const float* img = (const float*)d_in[0];
    float* out = (float*)d_out;
    float* coords  = out;
    float* weights = out + COORDS_ELEMS;
    float* dens    = out + COORDS_ELEMS + WEIGHTS_ELEMS;

    k_init<<<1, 32>>>();
    {
        dim3 grid(W / 32, H / 32, BATCH), block(32, 8);
        k_contrast<<<grid, block>>>(img);
    }
    {
        dim3 grid(W / 32, H / 32, BATCH), block(32, 8);
        k_density<<<grid, block>>>(dens);
    }
    k_coords<<<(BATCH*NCELL)/256, 256>>>(dens, coords, weights);
}

// round 4
// speedup vs baseline: 2.0054x; 1.0145x over previous
#include <cuda_runtime.h>
#include <cstdint>

// Problem constants (fixed by setup_inputs)
#define BATCH 8
#define H 1024
#define W 1024
#define HW (H*W)
#define TH 512
#define TW 512
#define NCELL (TH*TW)                    // 262144 = 2^18
#define COORDS_ELEMS (BATCH*NCELL*4*2)   // 16777216
#define WEIGHTS_ELEMS (BATCH*NCELL*4)    // 8388608

// Scratch (static device globals — allocation-free per harness rules)
__device__ float g_contrast[BATCH*HW];
__device__ unsigned g_mn[BATCH];
__device__ unsigned g_mx[BATCH];

// ---------------------------------------------------------------------------
// JAX threefry2x32, key = jax.random.key(42) -> (0, 42)
// ---------------------------------------------------------------------------
__device__ __forceinline__ unsigned rotl32(unsigned x, int r) {
    return __funnelshift_l(x, x, r);
}

__device__ __forceinline__ void threefry2x32(unsigned x0, unsigned x1,
                                             unsigned& o0, unsigned& o1) {
    const unsigned ks0 = 0u, ks1 = 42u, ks2 = 0x1BD11BF0u;
    x0 += ks0; x1 += ks1;
#define TFR(r) { x0 += x1; x1 = rotl32(x1, r); x1 ^= x0; }
    TFR(13) TFR(15) TFR(26) TFR(6)
    x0 += ks1; x1 += ks2 + 1u;
    TFR(17) TFR(29) TFR(16) TFR(24)
    x0 += ks2; x1 += ks0 + 2u;
    TFR(13) TFR(15) TFR(26) TFR(6)
    x0 += ks0; x1 += ks1 + 3u;
    TFR(17) TFR(29) TFR(16) TFR(24)
    x0 += ks1; x1 += ks2 + 4u;
    TFR(13) TFR(15) TFR(26) TFR(6)
    x0 += ks2; x1 += ks0 + 5u;
#undef TFR
    o0 = x0; o1 = x1;
}

__device__ __forceinline__ float tf_uniform(unsigned flat_idx) {
    unsigned o0, o1;
    threefry2x32(0u, flat_idx, o0, o1);
    unsigned bits = o0 ^ o1;
    return __uint_as_float((bits >> 9) | 0x3f800000u) - 1.0f;
}

// ---------------------------------------------------------------------------
// Kernel 0: reset per-batch min/max (must run every call: graph replays)
// ---------------------------------------------------------------------------
__global__ void k_init() {
    int i = threadIdx.x;
    if (i < BATCH) { g_mn[i] = 0x7F800000u; g_mx[i] = 0u; }
}

// ---------------------------------------------------------------------------
// Kernel 1: fused gray + contrast + per-batch min/max.
// Tile 32x32 outputs per block (block 32x8, 4 rows/thread), gray halo 2 ->
// smem 36x36 gray computed straight from img. Zero-pad outside image.
// ---------------------------------------------------------------------------
__global__ void k_contrast(const float* __restrict__ img) {
    __shared__ float sg[36][37];
    __shared__ float wmn[8], wmx[8];

    const int b   = blockIdx.z;
    const int bx0 = blockIdx.x * 32;
    const int by0 = blockIdx.y * 32;
    const int tx = threadIdx.x, ty = threadIdx.y;
    const int lin = ty * 32 + tx;

    const float* ib = img + (size_t)b * 3 * HW;

    for (int e = lin; e < 36 * 36; e += 256) {
        int r = e / 36, c = e - r * 36;
        int gy = by0 + r - 2, gx = bx0 + c - 2;
        float v = 0.0f;
        if ((unsigned)gy < H && (unsigned)gx < W) {
            int p = gy * W + gx;
            v = __ldg(ib + p) * 0.299f + __ldg(ib + HW + p) * 0.587f
              + __ldg(ib + 2 * HW + p) * 0.114f;
        }
        sg[r][c] = v;
    }
    __syncthreads();

    const int x = bx0 + tx;
    const int lx = tx + 2;
    int xl = (x == 0) ? 0 : ((x == W-1) ? W-3 : x-1);
    int xr = (x == 0) ? 2 : ((x == W-1) ? W-1 : x+1);
    const int lxl = xl - bx0 + 2, lxr = xr - bx0 + 2;

    float cmin = 3.402823466e+38f, cmax = 0.0f;

#pragma unroll
    for (int k = 0; k < 4; ++k) {
        const int ry = ty + 8 * k;
        const int y = by0 + ry;
        const int ly = ry + 2;

        float a00 = sg[ly-1][lx-1], a01 = sg[ly-1][lx], a02 = sg[ly-1][lx+1];
        float a10 = sg[ly  ][lx-1], a11 = sg[ly  ][lx], a12 = sg[ly  ][lx+1];
        float a20 = sg[ly+1][lx-1], a21 = sg[ly+1][lx], a22 = sg[ly+1][lx+1];

        float gx2 = (a02 - a00) + 2.0f * (a12 - a10) + (a22 - a20);
        float gy2 = (a20 - a00) + 2.0f * (a21 - a01) + (a22 - a02);
        float sobel = sqrtf(gx2 * gx2 + gy2 * gy2 + 1e-8f);
        float lapl  = fabsf(4.0f * a11 - a01 - a10 - a12 - a21);

        int yl = (y == 0) ? 0 : ((y == H-1) ? H-3 : y-1);
        int yr = (y == 0) ? 2 : ((y == H-1) ? H-1 : y+1);
        float dx = sg[ly][lxr] - sg[ly][lxl];
        float dy = sg[yr - by0 + 2][lx] - sg[yl - by0 + 2][lx];
        float gradm = sqrtf(dx * dx + dy * dy + 1e-8f);

        float c = 0.5f * sobel + 0.3f * lapl + 0.2f * gradm;
        g_contrast[b * HW + y * W + x] = c;
        cmin = fminf(cmin, c);
        cmax = fmaxf(cmax, c);
    }

#pragma unroll
    for (int s = 16; s > 0; s >>= 1) {
        cmin = fminf(cmin, __shfl_xor_sync(0xFFFFFFFFu, cmin, s));
        cmax = fmaxf(cmax, __shfl_xor_sync(0xFFFFFFFFu, cmax, s));
    }
    if (tx == 0) { wmn[ty] = cmin; wmx[ty] = cmax; }
    __syncthreads();
    if (lin == 0) {
        float mn = wmn[0], mx = wmx[0];
#pragma unroll
        for (int s = 1; s < 8; ++s) {
            mn = fminf(mn, wmn[s]);
            mx = fmaxf(mx, wmx[s]);
        }
        atomicMin(&g_mn[b], __float_as_uint(mn));
        atomicMax(&g_mx[b], __float_as_uint(mx));
    }
}

// ---------------------------------------------------------------------------
// Kernel 2 (FUSED density + coords):
// Phase A: separable 5x5 gaussian with normalization folded out ->
//   density = 0.1 + 0.9*sqrt(max(inv*(conv - mn*wyv*wxv), 0)), 32x32 tile,
//   stored to dens_out AND even-even sub-grid staged into smem (16x16).
// Phase B: each thread owns one sampling cell (16x16 cells per tile),
//   generates threefry offsets + weights. This overlaps density's
//   LSU/FMA-heavy phase with the ALU-saturated threefry phase across
//   resident blocks.
// ---------------------------------------------------------------------------
__global__ void k_denscoords(float* __restrict__ dens_out,
                             float* __restrict__ coords,
                             float* __restrict__ weights) {
    __shared__ float raw[36][36];
    __shared__ float hac[36][32];
    __shared__ float sd[16][16];

    const int b   = blockIdx.z;
    const int bx0 = blockIdx.x * 32;
    const int by0 = blockIdx.y * 32;
    const int tx = threadIdx.x, ty = threadIdx.y;
    const int lin = ty * 32 + tx;

    // gaussian weights (same fp path as reference)
    const float sg2 = (5.0f / 6.0f) * (5.0f / 6.0f);
    const float e1 = expf(-0.5f / sg2);
    const float e2 = expf(-2.0f / sg2);
    const float ksum = 1.0f + 2.0f * e1 + 2.0f * e2;
    float w[5];
    w[0] = e2 / ksum; w[1] = e1 / ksum; w[2] = 1.0f / ksum; w[3] = w[1]; w[4] = w[0];

    const float* cb = g_contrast + b * HW;

    for (int e = lin; e < 36 * 36; e += 256) {
        int r = e / 36, c = e - r * 36;
        int gy = by0 + r - 2, gx = bx0 + c - 2;
        raw[r][c] = ((unsigned)gy < H && (unsigned)gx < W) ? cb[gy * W + gx] : 0.0f;
    }
    __syncthreads();

    for (int e = lin; e < 36 * 32; e += 256) {
        int r = e >> 5, c = e & 31;
        float a = w[0] * raw[r][c]     + w[1] * raw[r][c + 1]
                + w[2] * raw[r][c + 2] + w[3] * raw[r][c + 3]
                + w[4] * raw[r][c + 4];
        hac[r][c] = a;
    }
    __syncthreads();

    const float mn = __uint_as_float(g_mn[b]);
    const float mx = __uint_as_float(g_mx[b]);
    const bool ok = mx > mn;
    const float inv = ok ? 1.0f / (mx - mn) : 0.0f;

    const int x = bx0 + tx;
    float wxv = 0.0f;
#pragma unroll
    for (int d = 0; d < 5; ++d)
        if ((unsigned)(x + d - 2) < W) wxv += w[d];

#pragma unroll
    for (int k = 0; k < 4; ++k) {
        int ry = ty + 8 * k;
        int y = by0 + ry;
        float acc = w[0] * hac[ry][tx]     + w[1] * hac[ry + 1][tx]
                  + w[2] * hac[ry + 2][tx] + w[3] * hac[ry + 3][tx]
                  + w[4] * hac[ry + 4][tx];
        float wyv = 0.0f;
#pragma unroll
        for (int d = 0; d < 5; ++d)
            if ((unsigned)(y + d - 2) < H) wyv += w[d];
        float sm = inv * (acc - mn * (wyv * wxv));
        float dv = 0.1f + 0.9f * sqrtf(fmaxf(sm, 0.0f));
        dens_out[b * HW + y * W + x] = dv;
        // stage even-even pixels for the cell pass
        if (((ry & 1) | (tx & 1)) == 0) sd[ry >> 1][tx >> 1] = dv;
    }
    __syncthreads();

    // ---- Phase B: one cell per thread (16x16 cells in this tile) ----
    const int ci = lin >> 4;          // 0..15
    const int cj = lin & 15;          // 0..15
    const int i = (by0 >> 1) + ci;    // 0..511
    const int j = (bx0 >> 1) + cj;    // 0..511
    const int t = b * NCELL + i * TW + j;

    float d = sd[ci][cj];
    int ns = (d > 0.7f) ? 4 : ((d > 0.4f) ? 2 : 1);
    float wv = d / (float)ns;

    float by = -1.0f + (float)i * (2.0f / 511.0f);
    float bx = -1.0f + (float)j * (2.0f / 511.0f);
    const float CELLSZ = 0.00390625f;   // 2/512 exact

    float4 c0, c1;
    if (ns > 1) {
        unsigned ctr = (unsigned)t * 8u;
        float u[8];
#pragma unroll
        for (int s = 0; s < 8; ++s) u[s] = tf_uniform(ctr + s);
        c0.x = by + ((u[0] - 0.5f) * 0.8f) * CELLSZ;
        c0.y = bx + ((u[1] - 0.5f) * 0.8f) * CELLSZ;
        c0.z = by + ((u[2] - 0.5f) * 0.8f) * CELLSZ;
        c0.w = bx + ((u[3] - 0.5f) * 0.8f) * CELLSZ;
        c1.x = by + ((u[4] - 0.5f) * 0.8f) * CELLSZ;
        c1.y = bx + ((u[5] - 0.5f) * 0.8f) * CELLSZ;
        c1.z = by + ((u[6] - 0.5f) * 0.8f) * CELLSZ;
        c1.w = bx + ((u[7] - 0.5f) * 0.8f) * CELLSZ;
    } else {
        c0.x = by; c0.y = bx; c0.z = by; c0.w = bx;
        c1.x = by; c1.y = bx; c1.z = by; c1.w = bx;
    }

    float4* cp = (float4*)coords;
    cp[(size_t)t * 2]     = c0;
    cp[(size_t)t * 2 + 1] = c1;

    float4 w4;
    w4.x = wv;
    w4.y = (ns > 1) ? wv : 0.0f;
    w4.z = (ns > 3) ? wv : 0.0f;
    w4.w = (ns > 3) ? wv : 0.0f;
    ((float4*)weights)[t] = w4;
}

// ---------------------------------------------------------------------------
extern "C" void kernel_launch(void* const* d_in, const int* in_sizes, int n_in,
                              void* d_out, int out_size) {
    const float* img = (const float*)d_in[0];
    float* out = (float*)d_out;
    float* coords  = out;
    float* weights = out + COORDS_ELEMS;
    float* dens    = out + COORDS_ELEMS + WEIGHTS_ELEMS;

    k_init<<<1, 32>>>();
    {
        dim3 grid(W / 32, H / 32, BATCH), block(32, 8);
        k_contrast<<<grid, block>>>(img);
    }
    {
        dim3 grid(W / 32, H / 32, BATCH), block(32, 8);
        k_denscoords<<<grid, block>>>(dens, coords, weights);
    }
}

// round 5
// speedup vs baseline: 2.0956x; 1.0450x over previous
#include <cuda_runtime.h>
#include <cstdint>

// Problem constants (fixed by setup_inputs)
#define BATCH 8
#define H 1024
#define W 1024
#define HW (H*W)
#define TH 512
#define TW 512
#define NCELL (TH*TW)                    // 262144 = 2^18
#define COORDS_ELEMS (BATCH*NCELL*4*2)   // 16777216
#define WEIGHTS_ELEMS (BATCH*NCELL*4)    // 8388608
#define NTILES 1024                      // 32x32 tiles per image
#define NCONTRAST (BATCH*NTILES)         // 8192

// Scratch (static device globals — allocation-free per harness rules)
__device__ float g_contrast[BATCH*HW];
__device__ float g_bmn[NCONTRAST];       // per-contrast-block min
__device__ float g_bmx[NCONTRAST];       // per-contrast-block max

// ---------------------------------------------------------------------------
// JAX threefry2x32, key = jax.random.key(42) -> (0, 42)
// ---------------------------------------------------------------------------
__device__ __forceinline__ unsigned rotl32(unsigned x, int r) {
    return __funnelshift_l(x, x, r);
}

__device__ __forceinline__ void threefry2x32(unsigned x0, unsigned x1,
                                             unsigned& o0, unsigned& o1) {
    const unsigned ks0 = 0u, ks1 = 42u, ks2 = 0x1BD11BF0u;
    x0 += ks0; x1 += ks1;
#define TFR(r) { x0 += x1; x1 = rotl32(x1, r); x1 ^= x0; }
    TFR(13) TFR(15) TFR(26) TFR(6)
    x0 += ks1; x1 += ks2 + 1u;
    TFR(17) TFR(29) TFR(16) TFR(24)
    x0 += ks2; x1 += ks0 + 2u;
    TFR(13) TFR(15) TFR(26) TFR(6)
    x0 += ks0; x1 += ks1 + 3u;
    TFR(17) TFR(29) TFR(16) TFR(24)
    x0 += ks1; x1 += ks2 + 4u;
    TFR(13) TFR(15) TFR(26) TFR(6)
    x0 += ks2; x1 += ks0 + 5u;
#undef TFR
    o0 = x0; o1 = x1;
}

__device__ __forceinline__ float tf_uniform(unsigned flat_idx) {
    unsigned o0, o1;
    threefry2x32(0u, flat_idx, o0, o1);
    unsigned bits = o0 ^ o1;
    return __uint_as_float((bits >> 9) | 0x3f800000u) - 1.0f;
}

// ---------------------------------------------------------------------------
// K1: interleaved fat kernel. Even bid -> contrast tile (mem-bound),
// odd bid -> threefry coords offsets (alu-bound, img-independent).
// The two block types co-reside on each SM: alu issue hides DRAM latency.
// ---------------------------------------------------------------------------
__global__ void k_main1(const float* __restrict__ img,
                        float* __restrict__ coords) {
    __shared__ float sg[36][37];
    __shared__ float wmn[8], wmx[8];

    const int bid = blockIdx.x;
    const int lin = threadIdx.x;

    if ((bid & 1) == 0) {
        // ---------------- contrast tile ----------------
        const int cid = bid >> 1;            // 0..8191
        const int b    = cid >> 10;
        const int tile = cid & (NTILES - 1);
        const int by0 = (tile >> 5) * 32;
        const int bx0 = (tile & 31) * 32;
        const int tx = lin & 31, ty = lin >> 5;

        const float* ib = img + (size_t)b * 3 * HW;

        for (int e = lin; e < 36 * 36; e += 256) {
            int r = e / 36, c = e - r * 36;
            int gy = by0 + r - 2, gx = bx0 + c - 2;
            float v = 0.0f;
            if ((unsigned)gy < H && (unsigned)gx < W) {
                int p = gy * W + gx;
                v = __ldg(ib + p) * 0.299f + __ldg(ib + HW + p) * 0.587f
                  + __ldg(ib + 2 * HW + p) * 0.114f;
            }
            sg[r][c] = v;
        }
        __syncthreads();

        const int x = bx0 + tx;
        const int lx = tx + 2;
        int xl = (x == 0) ? 0 : ((x == W-1) ? W-3 : x-1);
        int xr = (x == 0) ? 2 : ((x == W-1) ? W-1 : x+1);
        const int lxl = xl - bx0 + 2, lxr = xr - bx0 + 2;

        float cmin = 3.402823466e+38f, cmax = 0.0f;

#pragma unroll
        for (int k = 0; k < 4; ++k) {
            const int ry = ty + 8 * k;
            const int y = by0 + ry;
            const int ly = ry + 2;

            float a00 = sg[ly-1][lx-1], a01 = sg[ly-1][lx], a02 = sg[ly-1][lx+1];
            float a10 = sg[ly  ][lx-1], a11 = sg[ly  ][lx], a12 = sg[ly  ][lx+1];
            float a20 = sg[ly+1][lx-1], a21 = sg[ly+1][lx], a22 = sg[ly+1][lx+1];

            float gx2 = (a02 - a00) + 2.0f * (a12 - a10) + (a22 - a20);
            float gy2 = (a20 - a00) + 2.0f * (a21 - a01) + (a22 - a02);
            float sobel = sqrtf(gx2 * gx2 + gy2 * gy2 + 1e-8f);
            float lapl  = fabsf(4.0f * a11 - a01 - a10 - a12 - a21);

            int yl = (y == 0) ? 0 : ((y == H-1) ? H-3 : y-1);
            int yr = (y == 0) ? 2 : ((y == H-1) ? H-1 : y+1);
            float dx = sg[ly][lxr] - sg[ly][lxl];
            float dy = sg[yr - by0 + 2][lx] - sg[yl - by0 + 2][lx];
            float gradm = sqrtf(dx * dx + dy * dy + 1e-8f);

            float c = 0.5f * sobel + 0.3f * lapl + 0.2f * gradm;
            g_contrast[b * HW + y * W + x] = c;
            cmin = fminf(cmin, c);
            cmax = fmaxf(cmax, c);
        }

#pragma unroll
        for (int s = 16; s > 0; s >>= 1) {
            cmin = fminf(cmin, __shfl_xor_sync(0xFFFFFFFFu, cmin, s));
            cmax = fmaxf(cmax, __shfl_xor_sync(0xFFFFFFFFu, cmax, s));
        }
        if (tx == 0) { wmn[ty] = cmin; wmx[ty] = cmax; }
        __syncthreads();
        if (lin == 0) {
            float mn = wmn[0], mx = wmx[0];
#pragma unroll
            for (int s = 1; s < 8; ++s) {
                mn = fminf(mn, wmn[s]);
                mx = fmaxf(mx, wmx[s]);
            }
            g_bmn[cid] = mn;
            g_bmx[cid] = mx;
        }
    } else {
        // ---------------- coords offsets (img-independent) ----------------
        const int t = (bid >> 1) * 256 + lin;   // 0 .. 2M-1
        const int cell = t & (NCELL - 1);
        const int i = cell >> 9;
        const int j = cell & (TW - 1);

        float by = -1.0f + (float)i * (2.0f / 511.0f);
        float bx = -1.0f + (float)j * (2.0f / 511.0f);
        const float CELLSZ = 0.00390625f;   // 2/512 exact

        unsigned ctr = (unsigned)t * 8u;
        float u[8];
#pragma unroll
        for (int s = 0; s < 8; ++s) u[s] = tf_uniform(ctr + s);

        float4 c0, c1;
        c0.x = by + ((u[0] - 0.5f) * 0.8f) * CELLSZ;
        c0.y = bx + ((u[1] - 0.5f) * 0.8f) * CELLSZ;
        c0.z = by + ((u[2] - 0.5f) * 0.8f) * CELLSZ;
        c0.w = bx + ((u[3] - 0.5f) * 0.8f) * CELLSZ;
        c1.x = by + ((u[4] - 0.5f) * 0.8f) * CELLSZ;
        c1.y = bx + ((u[5] - 0.5f) * 0.8f) * CELLSZ;
        c1.z = by + ((u[6] - 0.5f) * 0.8f) * CELLSZ;
        c1.w = bx + ((u[7] - 0.5f) * 0.8f) * CELLSZ;

        float4* cp = (float4*)coords;
        cp[(size_t)t * 2]     = c0;
        cp[(size_t)t * 2 + 1] = c1;
    }
}

// ---------------------------------------------------------------------------
// K2: per-batch min/max re-reduce (1024 block results) + separable 5x5
// gaussian density + weights + coords fixup for ns==1 cells.
// Block (32,8) over a 32x32 tile.
// ---------------------------------------------------------------------------
__global__ void k_main2(float* __restrict__ dens_out,
                        float* __restrict__ coords,
                        float* __restrict__ weights) {
    __shared__ float raw[36][36];
    __shared__ float hac[36][32];
    __shared__ float sd[16][16];
    __shared__ float rmn[8], rmx[8];

    const int b   = blockIdx.z;
    const int bx0 = blockIdx.x * 32;
    const int by0 = blockIdx.y * 32;
    const int tx = threadIdx.x, ty = threadIdx.y;
    const int lin = ty * 32 + tx;

    // --- batch min/max from per-block results (exact: min/max associative)
    {
        float mn = 3.402823466e+38f, mx = 0.0f;
        for (int e = lin; e < NTILES; e += 256) {
            mn = fminf(mn, g_bmn[b * NTILES + e]);
            mx = fmaxf(mx, g_bmx[b * NTILES + e]);
        }
#pragma unroll
        for (int s = 16; s > 0; s >>= 1) {
            mn = fminf(mn, __shfl_xor_sync(0xFFFFFFFFu, mn, s));
            mx = fmaxf(mx, __shfl_xor_sync(0xFFFFFFFFu, mx, s));
        }
        if (tx == 0) { rmn[ty] = mn; rmx[ty] = mx; }
    }

    // gaussian weights (same fp path as reference)
    const float sg2 = (5.0f / 6.0f) * (5.0f / 6.0f);
    const float e1 = expf(-0.5f / sg2);
    const float e2 = expf(-2.0f / sg2);
    const float ksum = 1.0f + 2.0f * e1 + 2.0f * e2;
    float w[5];
    w[0] = e2 / ksum; w[1] = e1 / ksum; w[2] = 1.0f / ksum; w[3] = w[1]; w[4] = w[0];

    const float* cb = g_contrast + b * HW;

    for (int e = lin; e < 36 * 36; e += 256) {
        int r = e / 36, c = e - r * 36;
        int gy = by0 + r - 2, gx = bx0 + c - 2;
        raw[r][c] = ((unsigned)gy < H && (unsigned)gx < W) ? cb[gy * W + gx] : 0.0f;
    }
    __syncthreads();

    float mn = rmn[0], mx = rmx[0];
#pragma unroll
    for (int s = 1; s < 8; ++s) {
        mn = fminf(mn, rmn[s]);
        mx = fmaxf(mx, rmx[s]);
    }
    const bool ok = mx > mn;
    const float inv = ok ? 1.0f / (mx - mn) : 0.0f;

    for (int e = lin; e < 36 * 32; e += 256) {
        int r = e >> 5, c = e & 31;
        float a = w[0] * raw[r][c]     + w[1] * raw[r][c + 1]
                + w[2] * raw[r][c + 2] + w[3] * raw[r][c + 3]
                + w[4] * raw[r][c + 4];
        hac[r][c] = a;
    }
    __syncthreads();

    const int x = bx0 + tx;
    float wxv = 0.0f;
#pragma unroll
    for (int d = 0; d < 5; ++d)
        if ((unsigned)(x + d - 2) < W) wxv += w[d];

#pragma unroll
    for (int k = 0; k < 4; ++k) {
        int ry = ty + 8 * k;
        int y = by0 + ry;
        float acc = w[0] * hac[ry][tx]     + w[1] * hac[ry + 1][tx]
                  + w[2] * hac[ry + 2][tx] + w[3] * hac[ry + 3][tx]
                  + w[4] * hac[ry + 4][tx];
        float wyv = 0.0f;
#pragma unroll
        for (int d = 0; d < 5; ++d)
            if ((unsigned)(y + d - 2) < H) wyv += w[d];
        float sm = inv * (acc - mn * (wyv * wxv));
        float dv = 0.1f + 0.9f * sqrtf(fmaxf(sm, 0.0f));
        dens_out[b * HW + y * W + x] = dv;
        if (((ry & 1) | (tx & 1)) == 0) sd[ry >> 1][tx >> 1] = dv;
    }
    __syncthreads();

    // ---- per-cell weights + coords fixup ----
    const int ci = lin >> 4;
    const int cj = lin & 15;
    const int i = (by0 >> 1) + ci;
    const int j = (bx0 >> 1) + cj;
    const int t = b * NCELL + i * TW + j;

    float d = sd[ci][cj];
    int ns = (d > 0.7f) ? 4 : ((d > 0.4f) ? 2 : 1);
    float wv = d / (float)ns;

    float4 w4;
    w4.x = wv;
    w4.y = (ns > 1) ? wv : 0.0f;
    w4.z = (ns > 3) ? wv : 0.0f;
    w4.w = (ns > 3) ? wv : 0.0f;
    ((float4*)weights)[t] = w4;

    if (ns == 1) {
        float by = -1.0f + (float)i * (2.0f / 511.0f);
        float bx = -1.0f + (float)j * (2.0f / 511.0f);
        float4 c0; c0.x = by; c0.y = bx; c0.z = by; c0.w = bx;
        float4* cp = (float4*)coords;
        cp[(size_t)t * 2]     = c0;
        cp[(size_t)t * 2 + 1] = c0;
    }
}

// ---------------------------------------------------------------------------
extern "C" void kernel_launch(void* const* d_in, const int* in_sizes, int n_in,
                              void* d_out, int out_size) {
    const float* img = (const float*)d_in[0];
    float* out = (float*)d_out;
    float* coords  = out;
    float* weights = out + COORDS_ELEMS;
    float* dens    = out + COORDS_ELEMS + WEIGHTS_ELEMS;

    k_main1<<<2 * NCONTRAST, 256>>>(img, coords);
    {
        dim3 grid(W / 32, H / 32, BATCH), block(32, 8);
        k_main2<<<grid, block>>>(dens, coords, weights);
    }
}

// round 6
// speedup vs baseline: 2.3765x; 1.1341x over previous
#include <cuda_runtime.h>
#include <cstdint>

// Problem constants (fixed by setup_inputs)
#define BATCH 8
#define H 1024
#define W 1024
#define HW (H*W)
#define TH 512
#define TW 512
#define NCELL (TH*TW)                    // 262144 = 2^18
#define COORDS_ELEMS (BATCH*NCELL*4*2)   // 16777216
#define WEIGHTS_ELEMS (BATCH*NCELL*4)    // 8388608
#define NTILES 1024                      // 32x32 tiles per image
#define NCONTRAST (BATCH*NTILES)         // 8192

// Scratch (static device globals — allocation-free per harness rules)
__device__ float g_contrast[BATCH*HW];
__device__ float g_bmn[NCONTRAST];       // per-contrast-block min
__device__ float g_bmx[NCONTRAST];       // per-contrast-block max

// ---------------------------------------------------------------------------
// JAX threefry2x32, key = jax.random.key(42) -> (0, 42)
// ---------------------------------------------------------------------------
__device__ __forceinline__ unsigned rotl32(unsigned x, int r) {
    return __funnelshift_l(x, x, r);
}

__device__ __forceinline__ void threefry2x32(unsigned x0, unsigned x1,
                                             unsigned& o0, unsigned& o1) {
    const unsigned ks0 = 0u, ks1 = 42u, ks2 = 0x1BD11BF0u;
    x0 += ks0; x1 += ks1;
#define TFR(r) { x0 += x1; x1 = rotl32(x1, r); x1 ^= x0; }
    TFR(13) TFR(15) TFR(26) TFR(6)
    x0 += ks1; x1 += ks2 + 1u;
    TFR(17) TFR(29) TFR(16) TFR(24)
    x0 += ks2; x1 += ks0 + 2u;
    TFR(13) TFR(15) TFR(26) TFR(6)
    x0 += ks0; x1 += ks1 + 3u;
    TFR(17) TFR(29) TFR(16) TFR(24)
    x0 += ks1; x1 += ks2 + 4u;
    TFR(13) TFR(15) TFR(26) TFR(6)
    x0 += ks2; x1 += ks0 + 5u;
#undef TFR
    o0 = x0; o1 = x1;
}

__device__ __forceinline__ float tf_uniform(unsigned flat_idx) {
    unsigned o0, o1;
    threefry2x32(0u, flat_idx, o0, o1);
    unsigned bits = o0 ^ o1;
    return __uint_as_float((bits >> 9) | 0x3f800000u) - 1.0f;
}

// ---------------------------------------------------------------------------
// K1: interleaved fat kernel. Even bid -> contrast tile (mem-bound),
// odd bid -> threefry coords offsets (alu-bound, img-independent).
// ---------------------------------------------------------------------------
__global__ void k_main1(const float* __restrict__ img,
                        float* __restrict__ coords) {
    __shared__ float sg[36][37];
    __shared__ float wmn[8], wmx[8];

    const int bid = blockIdx.x;
    const int lin = threadIdx.x;

    if ((bid & 1) == 0) {
        // ---------------- contrast tile ----------------
        const int cid = bid >> 1;            // 0..8191
        const int b    = cid >> 10;
        const int tile = cid & (NTILES - 1);
        const int by0 = (tile >> 5) * 32;
        const int bx0 = (tile & 31) * 32;
        const int tx = lin & 31, ty = lin >> 5;

        const float* ib = img + (size_t)b * 3 * HW;

        for (int e = lin; e < 36 * 36; e += 256) {
            int r = e / 36, c = e - r * 36;
            int gy = by0 + r - 2, gx = bx0 + c - 2;
            float v = 0.0f;
            if ((unsigned)gy < H && (unsigned)gx < W) {
                int p = gy * W + gx;
                v = __ldg(ib + p) * 0.299f + __ldg(ib + HW + p) * 0.587f
                  + __ldg(ib + 2 * HW + p) * 0.114f;
            }
            sg[r][c] = v;
        }
        __syncthreads();

        const int x = bx0 + tx;
        const int lx = tx + 2;
        int xl = (x == 0) ? 0 : ((x == W-1) ? W-3 : x-1);
        int xr = (x == 0) ? 2 : ((x == W-1) ? W-1 : x+1);
        const int lxl = xl - bx0 + 2, lxr = xr - bx0 + 2;

        float cmin = 3.402823466e+38f, cmax = 0.0f;

#pragma unroll
        for (int k = 0; k < 4; ++k) {
            const int ry = ty + 8 * k;
            const int y = by0 + ry;
            const int ly = ry + 2;

            float a00 = sg[ly-1][lx-1], a01 = sg[ly-1][lx], a02 = sg[ly-1][lx+1];
            float a10 = sg[ly  ][lx-1], a11 = sg[ly  ][lx], a12 = sg[ly  ][lx+1];
            float a20 = sg[ly+1][lx-1], a21 = sg[ly+1][lx], a22 = sg[ly+1][lx+1];

            float gx2 = (a02 - a00) + 2.0f * (a12 - a10) + (a22 - a20);
            float gy2 = (a20 - a00) + 2.0f * (a21 - a01) + (a22 - a02);
            float sobel = sqrtf(gx2 * gx2 + gy2 * gy2 + 1e-8f);
            float lapl  = fabsf(4.0f * a11 - a01 - a10 - a12 - a21);

            int yl = (y == 0) ? 0 : ((y == H-1) ? H-3 : y-1);
            int yr = (y == 0) ? 2 : ((y == H-1) ? H-1 : y+1);
            float dx = sg[ly][lxr] - sg[ly][lxl];
            float dy = sg[yr - by0 + 2][lx] - sg[yl - by0 + 2][lx];
            float gradm = sqrtf(dx * dx + dy * dy + 1e-8f);

            float c = 0.5f * sobel + 0.3f * lapl + 0.2f * gradm;
            g_contrast[b * HW + y * W + x] = c;
            cmin = fminf(cmin, c);
            cmax = fmaxf(cmax, c);
        }

#pragma unroll
        for (int s = 16; s > 0; s >>= 1) {
            cmin = fminf(cmin, __shfl_xor_sync(0xFFFFFFFFu, cmin, s));
            cmax = fmaxf(cmax, __shfl_xor_sync(0xFFFFFFFFu, cmax, s));
        }
        if (tx == 0) { wmn[ty] = cmin; wmx[ty] = cmax; }
        __syncthreads();
        if (lin == 0) {
            float mn = wmn[0], mx = wmx[0];
#pragma unroll
            for (int s = 1; s < 8; ++s) {
                mn = fminf(mn, wmn[s]);
                mx = fmaxf(mx, wmx[s]);
            }
            g_bmn[cid] = mn;
            g_bmx[cid] = mx;
        }
    } else {
        // ---------------- coords offsets (img-independent) ----------------
        const int t = (bid >> 1) * 256 + lin;   // 0 .. 2M-1
        const int cell = t & (NCELL - 1);
        const int i = cell >> 9;
        const int j = cell & (TW - 1);

        float by = -1.0f + (float)i * (2.0f / 511.0f);
        float bx = -1.0f + (float)j * (2.0f / 511.0f);
        const float CELLSZ = 0.00390625f;   // 2/512 exact

        unsigned ctr = (unsigned)t * 8u;
        float u[8];
#pragma unroll
        for (int s = 0; s < 8; ++s) u[s] = tf_uniform(ctr + s);

        float4 c0, c1;
        c0.x = by + ((u[0] - 0.5f) * 0.8f) * CELLSZ;
        c0.y = bx + ((u[1] - 0.5f) * 0.8f) * CELLSZ;
        c0.z = by + ((u[2] - 0.5f) * 0.8f) * CELLSZ;
        c0.w = bx + ((u[3] - 0.5f) * 0.8f) * CELLSZ;
        c1.x = by + ((u[4] - 0.5f) * 0.8f) * CELLSZ;
        c1.y = bx + ((u[5] - 0.5f) * 0.8f) * CELLSZ;
        c1.z = by + ((u[6] - 0.5f) * 0.8f) * CELLSZ;
        c1.w = bx + ((u[7] - 0.5f) * 0.8f) * CELLSZ;

        float4* cp = (float4*)coords;
        cp[(size_t)t * 2]     = c0;
        cp[(size_t)t * 2 + 1] = c1;
    }
}

// ---------------------------------------------------------------------------
// horizontal 5-tap of zero-padded contrast at row y, cols x4..x4+3.
// 3 aligned float4 loads (predicated at image edges / OOB rows -> 0).
// ---------------------------------------------------------------------------
__device__ __forceinline__ float4 hconv(const float* __restrict__ cb,
                                        int y, int x4,
                                        float w0, float w1, float w2,
                                        float w3, float w4) {
    float4 r;
    if ((unsigned)y >= H) { r.x = r.y = r.z = r.w = 0.0f; return r; }
    const float* rp = cb + y * W + x4;
    float f0,f1,f2,f3,f4,f5,f6,f7,f8,f9;
    if (x4 >= 4) {
        float4 a = *(const float4*)(rp - 4);
        f0 = a.z; f1 = a.w;          // cols x4-2, x4-1
    } else { f0 = f1 = 0.0f; }
    {
        float4 a = *(const float4*)rp;
        f2 = a.x; f3 = a.y; f4 = a.z; f5 = a.w;   // cols x4..x4+3
    }
    if (x4 + 4 < W) {
        float4 a = *(const float4*)(rp + 4);
        f6 = a.x; f7 = a.y;          // cols x4+4, x4+5
    } else { f6 = f7 = 0.0f; }
    r.x = w0*f0 + w1*f1 + w2*f2 + w3*f3 + w4*f4;
    r.y = w0*f1 + w1*f2 + w2*f3 + w3*f4 + w4*f5;
    r.z = w0*f2 + w1*f3 + w2*f4 + w3*f5 + w4*f6;
    r.w = w0*f3 + w1*f4 + w2*f5 + w3*f6 + w4*f7;
    (void)f8; (void)f9;
    return r;
}

// per-cell weights + ns==1 coords fixup (identical math to prior rounds)
__device__ __forceinline__ void do_cell(float d, int b, int i, int j,
                                        float* __restrict__ coords,
                                        float* __restrict__ weights) {
    int ns = (d > 0.7f) ? 4 : ((d > 0.4f) ? 2 : 1);
    float wv = d / (float)ns;
    int t = b * NCELL + i * TW + j;
    float4 w4;
    w4.x = wv;
    w4.y = (ns > 1) ? wv : 0.0f;
    w4.z = (ns > 3) ? wv : 0.0f;
    w4.w = (ns > 3) ? wv : 0.0f;
    ((float4*)weights)[t] = w4;
    if (ns == 1) {
        float by = -1.0f + (float)i * (2.0f / 511.0f);
        float bx = -1.0f + (float)j * (2.0f / 511.0f);
        float4 c0; c0.x = by; c0.y = bx; c0.z = by; c0.w = bx;
        float4* cp = (float4*)coords;
        cp[(size_t)t * 2]     = c0;
        cp[(size_t)t * 2 + 1] = c0;
    }
}

// ---------------------------------------------------------------------------
// K2': register-rolling separable gaussian + density + cells.
// Block (32,8) -> 128x128 tile; thread owns 4 cols (float4) x 16 rows.
// No smem tiles, no syncs in the mainloop.
// ---------------------------------------------------------------------------
__global__ void k_main2(float* __restrict__ dens_out,
                        float* __restrict__ coords,
                        float* __restrict__ weights) {
    __shared__ float rmn[8], rmx[8];

    const int b   = blockIdx.z;
    const int bx0 = blockIdx.x * 128;
    const int by0 = blockIdx.y * 128;
    const int tx = threadIdx.x, ty = threadIdx.y;
    const int lin = ty * 32 + tx;

    // --- batch min/max from per-block results (exact: min/max associative)
    {
        float mn_ = 3.402823466e+38f, mx_ = 0.0f;
        for (int e = lin; e < NTILES; e += 256) {
            mn_ = fminf(mn_, g_bmn[b * NTILES + e]);
            mx_ = fmaxf(mx_, g_bmx[b * NTILES + e]);
        }
#pragma unroll
        for (int s = 16; s > 0; s >>= 1) {
            mn_ = fminf(mn_, __shfl_xor_sync(0xFFFFFFFFu, mn_, s));
            mx_ = fmaxf(mx_, __shfl_xor_sync(0xFFFFFFFFu, mx_, s));
        }
        if (tx == 0) { rmn[ty] = mn_; rmx[ty] = mx_; }
    }
    __syncthreads();
    float mn = rmn[0], mx = rmx[0];
#pragma unroll
    for (int s = 1; s < 8; ++s) {
        mn = fminf(mn, rmn[s]);
        mx = fmaxf(mx, rmx[s]);
    }
    const bool ok = mx > mn;
    const float inv = ok ? 1.0f / (mx - mn) : 0.0f;

    // gaussian weights (same fp path as reference)
    const float sg2 = (5.0f / 6.0f) * (5.0f / 6.0f);
    const float e1 = expf(-0.5f / sg2);
    const float e2 = expf(-2.0f / sg2);
    const float ksum = 1.0f + 2.0f * e1 + 2.0f * e2;
    float w[5];
    w[0] = e2 / ksum; w[1] = e1 / ksum; w[2] = 1.0f / ksum; w[3] = w[1]; w[4] = w[0];
    const float w0 = w[0], w1 = w[1], w2 = w[2], w3 = w[3], w4 = w[4];
    // interior wyv/wxv value, same summation order as the predicated loop
    const float wsum = ((((w[0] + w[1]) + w[2]) + w[3]) + w[4]);

    const int x4 = bx0 + tx * 4;

    // per-lane wxv (predicated loop, exact same order as prior rounds)
    float wxv0 = 0.f, wxv1 = 0.f, wxv2 = 0.f, wxv3 = 0.f;
#pragma unroll
    for (int d = 0; d < 5; ++d) {
        if ((unsigned)(x4 + 0 + d - 2) < W) wxv0 += w[d];
        if ((unsigned)(x4 + 1 + d - 2) < W) wxv1 += w[d];
        if ((unsigned)(x4 + 2 + d - 2) < W) wxv2 += w[d];
        if ((unsigned)(x4 + 3 + d - 2) < W) wxv3 += w[d];
    }

    const float* cb = g_contrast + b * HW;
    const int ys = by0 + ty * 16;

    // rolling window of horizontal conv rows ys-2 .. ys+1
    float4 h0 = hconv(cb, ys - 2, x4, w0, w1, w2, w3, w4);
    float4 h1 = hconv(cb, ys - 1, x4, w0, w1, w2, w3, w4);
    float4 h2 = hconv(cb, ys,     x4, w0, w1, w2, w3, w4);
    float4 h3 = hconv(cb, ys + 1, x4, w0, w1, w2, w3, w4);

    float* drow = dens_out + b * HW + ys * W + x4;

#pragma unroll
    for (int s = 0; s < 16; ++s) {
        const int y = ys + s;
        float4 h4 = hconv(cb, y + 2, x4, w0, w1, w2, w3, w4);

        float4 acc;
        acc.x = w0*h0.x + w1*h1.x + w2*h2.x + w3*h3.x + w4*h4.x;
        acc.y = w0*h0.y + w1*h1.y + w2*h2.y + w3*h3.y + w4*h4.y;
        acc.z = w0*h0.z + w1*h1.z + w2*h2.z + w3*h3.z + w4*h4.z;
        acc.w = w0*h0.w + w1*h1.w + w2*h2.w + w3*h3.w + w4*h4.w;

        float wyv = wsum;
        if (y < 2 || y >= H - 2) {
            wyv = 0.0f;
#pragma unroll
            for (int d = 0; d < 5; ++d)
                if ((unsigned)(y + d - 2) < H) wyv += w[d];
        }

        float4 dv;
        dv.x = 0.1f + 0.9f * sqrtf(fmaxf(inv * (acc.x - mn * (wyv * wxv0)), 0.0f));
        dv.y = 0.1f + 0.9f * sqrtf(fmaxf(inv * (acc.y - mn * (wyv * wxv1)), 0.0f));
        dv.z = 0.1f + 0.9f * sqrtf(fmaxf(inv * (acc.z - mn * (wyv * wxv2)), 0.0f));
        dv.w = 0.1f + 0.9f * sqrtf(fmaxf(inv * (acc.w - mn * (wyv * wxv3)), 0.0f));

        *(float4*)drow = dv;
        drow += W;

        if ((y & 1) == 0) {
            const int i = y >> 1;
            const int j0 = x4 >> 1;
            do_cell(dv.x, b, i, j0,     coords, weights);
            do_cell(dv.z, b, i, j0 + 1, coords, weights);
        }

        h0 = h1; h1 = h2; h2 = h3; h3 = h4;
    }
}

// ---------------------------------------------------------------------------
extern "C" void kernel_launch(void* const* d_in, const int* in_sizes, int n_in,
                              void* d_out, int out_size) {
    const float* img = (const float*)d_in[0];
    float* out = (float*)d_out;
    float* coords  = out;
    float* weights = out + COORDS_ELEMS;
    float* dens    = out + COORDS_ELEMS + WEIGHTS_ELEMS;

    k_main1<<<2 * NCONTRAST, 256>>>(img, coords);
    {
        dim3 grid(W / 128, H / 128, BATCH), block(32, 8);
        k_main2<<<grid, block>>>(dens, coords, weights);
    }
}